// round 11
// baseline (speedup 1.0000x reference)
#include <cuda_runtime.h>
#include <math.h>

#define TWO_PI 6.283185307179586f
#define EPS 1e-6f
#define NEG_HALF_LOG2E (-0.7213475204444817f)

typedef unsigned long long u64;

// ---------------- device scratch ----------------
#define MAXM 120000        // per-component scalars (rows*N max = 192*625)
#define MAX4 60160         // packed float4 units (rows*half max = 192*313)
#define MAXS 4096
#define MAXROWS 320

// packed row tiles, pair-interleaved to match eval smem layout:
// g_A4[row*half+j] = (px[2j],px[2j+1],py[2j],py[2j+1])
// g_B4: (ea,ea,eb,eb)   g_C4: (ec,ec,w,w)
__device__ float4 g_A4[MAX4], g_B4[MAX4], g_C4[MAX4];
__device__ float g_C00[MAXM], g_C01[MAXM], g_C11[MAXM];
__device__ float g_W2[MAXM];

__device__ u64 g_cand[MAXROWS * 136];
__device__ int g_candcnt[MAXROWS];      // zero-init; reset by topk2 each use

__device__ float g_SW[MAXS], g_SPX[MAXS], g_SPY[MAXS];
__device__ float g_SC00[MAXS], g_SC01[MAXS], g_SC11[MAXS];

__device__ float g_TOT[MAXROWS], g_SIG[MAXROWS];
__device__ int g_tick = 0;              // finale ticket; self-resetting

__device__ __forceinline__ float fast_exp2(float x) {
    float y; asm("ex2.approx.ftz.f32 %0, %1;" : "=f"(y) : "f"(x)); return y;
}
__device__ __forceinline__ float fast_sqrt(float x) {
    float y; asm("sqrt.approx.ftz.f32 %0, %1;" : "=f"(y) : "f"(x)); return y;
}
__device__ __forceinline__ float fast_rcp(float x) {
    float y; asm("rcp.approx.ftz.f32 %0, %1;" : "=f"(y) : "f"(x)); return y;
}

// ---- packed f32x2 helpers ----
__device__ __forceinline__ u64 pk2(float lo, float hi) {
    u64 r; asm("mov.b64 %0, {%1, %2};" : "=l"(r) : "f"(lo), "f"(hi)); return r;
}
__device__ __forceinline__ void upk2(u64 v, float& lo, float& hi) {
    asm("mov.b64 {%0, %1}, %2;" : "=f"(lo), "=f"(hi) : "l"(v));
}
__device__ __forceinline__ u64 add2(u64 a, u64 b) {
    u64 r; asm("add.rn.f32x2 %0, %1, %2;" : "=l"(r) : "l"(a), "l"(b)); return r;
}
__device__ __forceinline__ u64 mul2(u64 a, u64 b) {
    u64 r; asm("mul.rn.f32x2 %0, %1, %2;" : "=l"(r) : "l"(a), "l"(b)); return r;
}
__device__ __forceinline__ u64 fma2(u64 a, u64 b, u64 c) {
    u64 r; asm("fma.rn.f32x2 %0, %1, %2, %3;" : "=l"(r) : "l"(a), "l"(b), "l"(c)); return r;
}

// ---------------- conv with fused batchnorm prologue ----------------
// grid: (ceil(Lo*N/256), B). Writes packed pair-interleaved tile arrays.
__global__ void k_conv(const float* __restrict__ in_x, const float* __restrict__ kern,
                       int Li, int Nd, int Lo, int Nk, int first) {
    __shared__ float s_scl[8];
    __shared__ float s_red[64];
    const int tid = threadIdx.x;
    const int b = blockIdx.y;
    const int N = Li * Nd * Nk;
    const int half = (N + 1) >> 1;

    if (first) {
        if (tid < 64) {
            const float* m = in_x + (b * 64 + tid) * 7;
            float det = m[3] * m[6] - m[4] * m[5];
            s_red[tid] = fabsf(m[0] * TWO_PI * fast_sqrt(fmaxf(det, EPS)));
        }
        __syncthreads();
        if (tid < 32) {
            float v = s_red[tid] + s_red[tid + 32];
            for (int o = 16; o > 0; o >>= 1) v += __shfl_xor_sync(0xffffffffu, v, o);
            if (tid == 0) s_scl[0] = 1.0f / (v + EPS);
        }
        __syncthreads();
    } else {
        if (tid < Li * 32) {
            int li = tid >> 5, bb = tid & 31;
            float v = g_TOT[bb * Li + li];
            for (int o = 16; o > 0; o >>= 1) v += __shfl_xor_sync(0xffffffffu, v, o);
            if ((tid & 31) == 0) s_scl[li] = 1.0f / (v * (1.0f / 32.0f) + EPS);
        }
        __syncthreads();
    }

    int perB = Lo * N;
    int i = blockIdx.x * 256 + tid;
    if (i >= perB) return;
    int lo = i / N;
    int c = i - lo * N;
    int nk = c % Nk;
    int nd = (c / Nk) % Nd;
    int li = c / (Nk * Nd);

    int di = (b * Li + li) * Nd + nd;
    float wd, pdx, pdy, d00, d01, d11;
    if (first) {
        const float* m = in_x + di * 7;
        wd = m[0] * s_scl[0]; pdx = m[1]; pdy = m[2];
        d00 = m[3]; d01 = m[4]; d11 = m[6];
    } else {
        wd = g_SW[di] * s_scl[li];
        pdx = g_SPX[di]; pdy = g_SPY[di];
        d00 = g_SC00[di]; d01 = g_SC01[di]; d11 = g_SC11[di];
    }

    const float* kp = kern + (((lo * Li + li) * Nk) + nk) * 7;
    float wk = kp[0], pkx = kp[1], pky = kp[2];
    float k00 = kp[3], k01 = kp[4], k11 = kp[6];

    float s00 = d00 + k00, s01 = d01 + k01, s11 = d11 + k11;
    float dd = d00 * d11 - d01 * d01;
    float dk = k00 * k11 - k01 * k01;
    float ds = s00 * s11 - s01 * s01;
    float inv = fast_rcp(fmaxf(ds, EPS));
    float ws = wd * wk * TWO_PI * fast_sqrt(dd * dk * inv);

    int row = b * Lo + lo;
    int u4 = (row * half + (c >> 1)) * 4 + (c & 1);
    ((float*)g_A4)[u4] = pdx + pkx;     ((float*)g_A4)[u4 + 2] = pdy + pky;
    ((float*)g_B4)[u4] = NEG_HALF_LOG2E * s11 * inv;
    ((float*)g_B4)[u4 + 2] = -NEG_HALF_LOG2E * (s01 + s01) * inv;
    ((float*)g_C4)[u4] = NEG_HALF_LOG2E * s00 * inv;
    ((float*)g_C4)[u4 + 2] = ws;

    int o = row * N + c;
    g_C00[o] = s00; g_C01[o] = s01; g_C11[o] = s11;
}

// ================= eval + level-1 rank epilogue =================
// grid (ceil(N/128), rows), block 128 = two 64-aligned chunks per block.
// Eval identical to R6. Tail: block writes its 128 keys to (dead) tile smem,
// each warp-half ranks within its 64-chunk; survivors (rank < nsel) appended
// to the row's global candidate list.
__global__ __launch_bounds__(128) void k_eval(
    int N, int Lo, int nsel, const float* __restrict__ bias)
{
    extern __shared__ __align__(16) float sh[];
    const int half = (N + 1) >> 1;
    float* sAf = sh;
    float* sBf = sh + 4 * half;
    float* sCf = sh + 8 * half;

    const int tid = threadIdx.x;
    const int row = blockIdx.y;
    const int base = row * N;
    const int rb4 = row * half;

    // ---- tile staging: packed float4 loads ----
    for (int u = tid; u < half; u += 128) {
        float4 a = g_A4[rb4 + u];
        float4 bq = g_B4[rb4 + u];
        float4 cq = g_C4[rb4 + u];
        if (2 * u + 1 >= N) {  // zero the pad lane (odd N)
            a.y = 0.0f; a.w = 0.0f;
            bq.y = 0.0f; bq.w = 0.0f;
            cq.y = 0.0f; cq.w = 0.0f;
        }
        ((float4*)sAf)[u] = a;
        ((float4*)sBf)[u] = bq;
        ((float4*)sCf)[u] = cq;
    }
    __syncthreads();

    // ---- eval (R6 inner loop) ----
    const int k = blockIdx.x * 128 + tid;
    u64 mykey = 0ull;
    if (k < N) {
        int k4 = (k >> 1) * 4 + (k & 1);
        float kx = sAf[k4], ky = sAf[k4 + 2];
        float wk = sCf[k4 + 2];
        u64 nkx2 = pk2(-kx, -kx);
        u64 nky2 = pk2(-ky, -ky);
        u64 acc = 0ull;

        const float4* sA = (const float4*)sAf;
        const float4* sB = (const float4*)sBf;
        const float4* sC = (const float4*)sCf;

        #pragma unroll 4
        for (int j = 0; j < half; j++) {
            float4 a = sA[j];
            float4 bq = sB[j];
            float4 c = sC[j];
            u64 px2 = *(const u64*)&a.x;  u64 py2 = *(const u64*)&a.z;
            u64 ea2 = *(const u64*)&bq.x; u64 eb2 = *(const u64*)&bq.z;
            u64 ec2 = *(const u64*)&c.x;  u64 w2p = *(const u64*)&c.z;

            u64 dx = add2(px2, nkx2);
            u64 dy = add2(py2, nky2);
            u64 u  = fma2(ea2, dx, mul2(eb2, dy));
            u64 md = fma2(dx, u, mul2(mul2(ec2, dy), dy));
            float m0, m1; upk2(md, m0, m1);
            u64 e = pk2(fast_exp2(m0), fast_exp2(m1));
            acc = fma2(w2p, e, acc);
        }

        float a0, a1; upk2(acc, a0, a1);
        float v = a0 + a1 + bias[row % Lo];
        float scale = fmaxf(v, 0.0f) * fast_rcp(fabsf(v) + EPS);
        float w2 = wk * scale;
        g_W2[base + k] = w2;
        mykey = ((u64)__float_as_uint(fabsf(w2)) << 32) | (u64)(unsigned)(~(unsigned)k);
    }

    // ---- level-1 rank within the block's two 64-chunks ----
    __syncthreads();                     // tile dead; overlay keys
    u64* keys = (u64*)sh;
    keys[tid] = mykey;
    __syncthreads();

    {
        int kb = tid & 64;               // 0 or 64: my chunk's base
        const ulonglong2* Q = (const ulonglong2*)(keys + kb);
        int r = 0;
        #pragma unroll 8
        for (int j = 0; j < 32; j++) {
            ulonglong2 q = Q[j];
            r += (int)(q.x > mykey) + (int)(q.y > mykey);
        }
        if (k < N && r < nsel) {
            int s = atomicAdd(&g_candcnt[row], 1);
            g_cand[row * 136 + s] = mykey;
        }
    }
}

// ---------------- topk level-2: rank candidates, gather, row sums ----------------
// grid rows, block 128. m <= 125 candidates per row.
__global__ void k_topk2(int N, int nsel, int do_final, int rows, float* __restrict__ out) {
    const int tid = threadIdx.x;
    const int row = blockIdx.x;
    const int base = row * N;
    const int half = (N + 1) >> 1;

    __shared__ __align__(16) u64 sCand[136];
    __shared__ int s_m, s_last;
    __shared__ float s_out[64];
    __shared__ float scl[10];
    __shared__ float logit[320];

    if (tid == 0) {
        int m = g_candcnt[row];
        g_candcnt[row] = 0;              // self-reset for graph replay
        s_m = m;
        sCand[m] = 0ull;                 // pad for u64x2 loads
    }
    __syncthreads();
    const int m = s_m;
    if (tid < m) sCand[tid] = g_cand[row * 136 + tid];
    __syncthreads();

    {
        int mq = (m + 1) >> 1;
        const ulonglong2* Q = (const ulonglong2*)sCand;
        if (tid < m) {
            u64 mykey = sCand[tid];
            int rank = 0;
            #pragma unroll 4
            for (int j = 0; j < mq; j++) {
                ulonglong2 q = Q[j];
                rank += (int)(q.x > mykey) + (int)(q.y > mykey);
            }
            if (rank < nsel) {
                int n = (int)(~(unsigned)mykey);
                int src = base + n;
                int dst = row * nsel + rank;
                float wv = g_W2[src];
                int u4 = (row * half + (n >> 1)) * 4 + (n & 1);
                float px = ((const float*)g_A4)[u4];
                float py = ((const float*)g_A4)[u4 + 2];
                float c00 = g_C00[src], c01 = g_C01[src], c11 = g_C11[src];
                g_SW[dst] = wv;
                g_SPX[dst] = px; g_SPY[dst] = py;
                g_SC00[dst] = c00; g_SC01[dst] = c01; g_SC11[dst] = c11;
                float I = wv * TWO_PI * fast_sqrt(fmaxf(c00 * c11 - c01 * c01, EPS));
                s_out[rank] = fabsf(I);
                s_out[32 + rank] = I;
            }
        }
    }
    __syncthreads();
    if (tid == 0) {
        float tot = 0.0f, sg = 0.0f;
        for (int t = 0; t < nsel; t++) { tot += s_out[t]; sg += s_out[32 + t]; }
        g_TOT[row] = tot;
        if (do_final) g_SIG[row] = sg;
    }

    if (!do_final) return;

    // ---- finale ticket (layer 3): bn + integrate + log_softmax ----
    if (tid == 0) {
        __threadfence();
        int t = atomicAdd(&g_tick, 1);
        s_last = (t == rows - 1) ? 1 : 0;
        if (s_last) g_tick = 0;
    }
    __syncthreads();
    if (!s_last) return;
    __threadfence();

    if (tid < 10) {
        float t = 0.0f;
        for (int b = 0; b < 32; b++) t += g_TOT[b * 10 + tid];
        scl[tid] = 1.0f / (t / 32.0f + EPS);
    }
    __syncthreads();
    for (int i = tid; i < 320; i += 128) logit[i] = g_SIG[i] * scl[i % 10];
    __syncthreads();
    if (tid < 32) {
        int b = tid;
        float mx = -INFINITY;
        for (int l = 0; l < 10; l++) mx = fmaxf(mx, logit[b * 10 + l]);
        float se = 0.0f;
        for (int l = 0; l < 10; l++) se += expf(logit[b * 10 + l] - mx);
        float lse = mx + logf(se);
        for (int l = 0; l < 10; l++) out[b * 10 + l] = logit[b * 10 + l] - lse;
    }
}

extern "C" void kernel_launch(void* const* d_in, const int* in_sizes, int n_in,
                              void* d_out, int out_size) {
    const float* in_x = (const float*)d_in[0];
    const float* k1 = (const float*)d_in[1];
    const float* k2 = (const float*)d_in[2];
    const float* k3 = (const float*)d_in[3];
    const float* b1 = (const float*)d_in[4];
    const float* b2 = (const float*)d_in[5];
    const float* b3 = (const float*)d_in[6];
    float* out = (float*)d_out;
    const int B = 32;

    // ===== layer 1: Li=1, Nd=64, Lo=5, Nk=5 -> N=320, rows=160, nsel=25 =====
    {
        int Li = 1, Nd = 64, Lo = 5, Nk = 5;
        int N = 320, rows = 160, perB = Lo * N;
        int half = (N + 1) >> 1;
        k_conv<<<dim3((perB + 255) / 256, B), 256>>>(in_x, k1, Li, Nd, Lo, Nk, 1);
        k_eval<<<dim3((N + 127) / 128, rows), 128, half * 48>>>(N, Lo, 25, b1);
        k_topk2<<<rows, 128>>>(N, 25, 0, rows, out);
    }

    // ===== layer 2: Li=5, Nd=25, Lo=6, Nk=5 -> N=625, rows=192, nsel=12 =====
    {
        int Li = 5, Nd = 25, Lo = 6, Nk = 5;
        int N = 625, rows = 192, perB = Lo * N;
        int half = (N + 1) >> 1;
        k_conv<<<dim3((perB + 255) / 256, B), 256>>>(in_x, k2, Li, Nd, Lo, Nk, 0);
        k_eval<<<dim3((N + 127) / 128, rows), 128, half * 48>>>(N, Lo, 12, b2);
        k_topk2<<<rows, 128>>>(N, 12, 0, rows, out);
    }

    // ===== layer 3: Li=6, Nd=12, Lo=10, Nk=5 -> N=360, rows=320, nsel=5 =====
    {
        int Li = 6, Nd = 12, Lo = 10, Nk = 5;
        int N = 360, rows = 320, perB = Lo * N;
        int half = (N + 1) >> 1;
        k_conv<<<dim3((perB + 255) / 256, B), 256>>>(in_x, k3, Li, Nd, Lo, Nk, 0);
        k_eval<<<dim3((N + 127) / 128, rows), 128, half * 48>>>(N, Lo, 5, b3);
        k_topk2<<<rows, 128>>>(N, 5, 1, rows, out);
    }
}